// round 16
// baseline (speedup 1.0000x reference)
#include <cuda_runtime.h>
#include <math.h>
#include <float.h>

#define NB 4
#define NF 64
#define NPTS 8192
#define NC 11
#define NG 8
#define NPER 1024
#define ND 192            // NF*3
#define NGB 32            // NG*NB
#define KSEL 16
#define NROWS (NGB*NPER)  // 32768

// ---------------- static device scratch ----------------
__device__ float g_Pe[NGB*NPER*ND];
__device__ float g_Pa[NGB*NPER*ND];
__device__ float g_Ve[NGB*NPER*ND];
__device__ float g_Va[NGB*NPER*ND];
__device__ float g_NPe[NGB*NPER*ND];
__device__ float g_NPa[NGB*NPER*ND];
__device__ float g_sPe[NROWS], g_sPa[NROWS], g_sNPe[NROWS], g_sNPa[NROWS];
__device__ float g_DG[(size_t)NGB*NPER*NPER];
__device__ float g_DN[(size_t)NGB*NPER*NPER];
__device__ float g_dgsum[NROWS], g_dnsum[NROWS], g_dvsum[NROWS];
__device__ int   g_idx[NROWS*KSEL];
__device__ int   g_rank[2*NPTS];
__device__ float g_partS[64*8*ND];
__device__ float g_partQ[64*8*ND];
__device__ float g_mean[64*3];
__device__ float g_inv[64*NF];

__device__ __forceinline__ float to_tf32(float x) {
    unsigned u;
    asm("cvt.rna.tf32.f32 %0, %1;" : "=r"(u) : "f"(x));
    return __uint_as_float(u);
}
__device__ __forceinline__ unsigned long long u64min(unsigned long long a, unsigned long long b) {
    return a < b ? a : b;
}

// ---------------- 1) fused group-id + stable counting sort -> rank ----------------
__global__ void rank_kernel(const float* __restrict__ E, const float* __restrict__ A) {
    __shared__ int sbg[NPTS];
    __shared__ int sh[NG][257];
    __shared__ int gbase[NG];
    int side = blockIdx.x;
    const float* X = side ? A : E;
    int t = threadIdx.x;
    int base = t*32;
    int cnt[NG];
    #pragma unroll
    for (int g = 0; g < NG; g++) cnt[g] = 0;
    for (int i = 0; i < 32; i++) {
        int p = base + i;
        float best = -FLT_MAX; int bi = 0;
        #pragma unroll
        for (int c = 0; c < NG; c++) {
            float v = X[(size_t)p*NC + 3 + c];
            if (v > best) { best = v; bi = c; }
        }
        sbg[p] = bi;
        cnt[bi]++;
    }
    #pragma unroll
    for (int g = 0; g < NG; g++) sh[g][t] = cnt[g];
    __syncthreads();
    if (t < NG) {
        int acc = 0;
        for (int i = 0; i < 256; i++) { int c = sh[t][i]; sh[t][i] = acc; acc += c; }
        sh[t][256] = acc;
    }
    __syncthreads();
    if (t == 0) {
        int acc = 0;
        for (int g = 0; g < NG; g++) { gbase[g] = acc; acc += sh[g][256]; }
    }
    __syncthreads();
    int run[NG];
    #pragma unroll
    for (int g = 0; g < NG; g++) run[g] = gbase[g] + sh[g][t];
    int* rk = g_rank + side*NPTS;
    for (int i = 0; i < 32; i++) { int g = sbg[base+i]; rk[base+i] = run[g]++; }
}

// ---------------- 2) build packed positions (rounded to tf32) ----------------
__global__ void build_kernel(const float* __restrict__ E, const float* __restrict__ A) {
    int tid = blockIdx.x*blockDim.x + threadIdx.x;
    int side = tid >> 21;
    int lin  = tid & ((1<<21)-1);
    int p = lin & (NPTS-1);
    int f = (lin >> 13) & (NF-1);
    int b = lin >> 19;
    const float* X = side ? A : E;
    size_t base = ((size_t)(b*NF + f)*NPTS + p)*NC;
    float x = X[base], y = X[base+1], z = X[base+2];
    int rk = g_rank[side*NPTS + p];
    int g = rk >> 10, j = rk & (NPER-1);
    int gb = g*NB + b;
    size_t o = ((size_t)(gb*NPER + j))*ND + f*3;
    float* P = side ? g_Pa : g_Pe;
    P[o] = to_tf32(x); P[o+1] = to_tf32(y); P[o+2] = to_tf32(z);
}

// ---------------- 3a) partial column sums ----------------
__global__ void __launch_bounds__(768) stats_part() {
    int sgb = blockIdx.x;
    int slice = blockIdx.y;
    int side = sgb >> 5, gb = sgb & 31;
    const float* P = (side ? g_Pa : g_Pe) + (size_t)gb*NPER*ND;
    int t = threadIdx.x % ND;
    int r = threadIdx.x / ND;
    __shared__ float Ss[4][ND];
    __shared__ float Qs[4][ND];
    float s = 0.f, q = 0.f;
    int j0 = slice*128;
    #pragma unroll 4
    for (int j = j0 + r; j < j0 + 128; j += 4) {
        float x = P[(size_t)j*ND + t];
        s += x; q += x*x;
    }
    Ss[r][t] = s; Qs[r][t] = q;
    __syncthreads();
    if (r == 0) {
        g_partS[(sgb*8 + slice)*ND + t] = Ss[0][t]+Ss[1][t]+Ss[2][t]+Ss[3][t];
        g_partQ[(sgb*8 + slice)*ND + t] = Qs[0][t]+Qs[1][t]+Qs[2][t]+Qs[3][t];
    }
}

// ---------------- 3b) finalize mean / invstd ----------------
__global__ void stats_final() {
    int sgb = blockIdx.x;
    int t = threadIdx.x;
    __shared__ float Ss[ND];
    __shared__ float Qs[ND];
    __shared__ float mean[3];
    float S = 0.f, Q = 0.f;
    #pragma unroll
    for (int sl = 0; sl < 8; sl++) {
        S += g_partS[(sgb*8 + sl)*ND + t];
        Q += g_partQ[(sgb*8 + sl)*ND + t];
    }
    Ss[t] = S; Qs[t] = Q;
    __syncthreads();
    if (t < 3) {
        float m = 0.f;
        for (int ff = 0; ff < NF; ff++) m += Ss[ff*3 + t];
        mean[t] = m / 65536.0f;
        g_mean[sgb*3 + t] = mean[t];
    }
    __syncthreads();
    if (t < NF) {
        float Sc = 0.f, Qc = 0.f;
        #pragma unroll
        for (int dd = 0; dd < 3; dd++) {
            float mu = mean[dd];
            float Sx = Ss[t*3+dd], Qx = Qs[t*3+dd];
            Sc += Sx - 1024.0f*mu;
            Qc += Qx - 2.0f*mu*Sx + 1024.0f*mu*mu;
        }
        float var = (Qc - Sc*Sc/3072.0f) / 3071.0f;   // ddof=1
        g_inv[sgb*NF + t] = 1.0f / sqrtf(fmaxf(var, 1e-30f));
    }
}

// ---------------- 3c) apply: normalize + velocity + BOTH row sqnorms ----------------
__global__ void __launch_bounds__(256) apply_kernel() {
    int w = blockIdx.x*8 + (threadIdx.x >> 5);
    int lane = threadIdx.x & 31;
    int side = w >> 15;
    int gb = (w >> 10) & 31;
    int j = w & (NPER-1);

    __shared__ float mu[3];
    __shared__ float inv[NF];
    int sgb0 = (blockIdx.x*8) >> 10;
    if (threadIdx.x < 3)  mu[threadIdx.x]  = g_mean[sgb0*3 + threadIdx.x];
    if (threadIdx.x < NF) inv[threadIdx.x] = g_inv[sgb0*NF + threadIdx.x];
    __syncthreads();

    size_t off = ((size_t)(gb*NPER + j))*ND;
    const float* P = (side ? g_Pa : g_Pe) + off;
    float* NP = (side ? g_NPa : g_NPe) + off;
    float* V  = (side ? g_Va  : g_Ve ) + off;

    float sP = 0.f, sNP = 0.f, prev = 0.f;
    #pragma unroll
    for (int i = 0; i < 6; i++) {
        int c = i*32 + lane;
        float x = P[c];
        float xm3a = __shfl_up_sync(0xffffffffu, x, 3);
        float xm3b = __shfl_sync(0xffffffffu, prev, (lane + 29) & 31);
        float xm3 = (lane >= 3) ? xm3a : xm3b;
        float v = (i == 0 && lane < 3) ? 0.f : (x - xm3);
        int d = c % 3, f = c / 3;
        float np = to_tf32((x - mu[d]) * inv[f]);
        NP[c] = np;
        V[c] = v;
        sP += x*x; sNP += np*np;
        prev = x;
    }
    #pragma unroll
    for (int o = 16; o; o >>= 1) {
        sP  += __shfl_down_sync(0xffffffffu, sP,  o);
        sNP += __shfl_down_sync(0xffffffffu, sNP, o);
    }
    if (!lane) {
        int row = w & (NROWS-1);
        (side ? g_sPa  : g_sPe )[row] = sP;
        (side ? g_sNPa : g_sNPe)[row] = sNP;
    }
}

// ---------------- 4) distance^2 via tf32 mma.sync (direct stores) ----------------
#define MMA_TF32(d, a, b) \
    asm volatile("mma.sync.aligned.m16n8k8.row.col.f32.tf32.tf32.f32 " \
        "{%0,%1,%2,%3}, {%4,%5,%6,%7}, {%8,%9}, {%0,%1,%2,%3};\n" \
        : "+f"(d[0]), "+f"(d[1]), "+f"(d[2]), "+f"(d[3]) \
        : "r"(a[0]), "r"(a[1]), "r"(a[2]), "r"(a[3]), "r"(b[0]), "r"(b[1]))

#define KC 16
#define KPAD 20

__global__ void __launch_bounds__(256) dist_kernel(int mode) {
    const float* A   = mode ? g_NPe  : g_Pe;
    const float* Bm  = mode ? g_NPa  : g_Pa;
    const float* sA  = mode ? g_sNPe : g_sPe;
    const float* sB  = mode ? g_sNPa : g_sPa;
    float*       D   = mode ? g_DN   : g_DG;

    int gb = blockIdx.z;
    const float* Ag = A  + (size_t)gb*NPER*ND;
    const float* Bg = Bm + (size_t)gb*NPER*ND;
    float*       Dg = D  + (size_t)gb*NPER*NPER;
    const float* sAg = sA + gb*NPER;
    const float* sBg = sB + gb*NPER;
    int row0 = blockIdx.y*128, col0 = blockIdx.x*128;

    __shared__ float As[2][128][KPAD];
    __shared__ float Bs[2][128][KPAD];

    int tid = threadIdx.x;
    int lane = tid & 31, wid = tid >> 5;
    int wm = wid >> 2, wn = wid & 3;
    int grp = lane >> 2, t4 = lane & 3;

    float acc[4][4][4];
    #pragma unroll
    for (int i = 0; i < 4; i++)
        #pragma unroll
        for (int j = 0; j < 4; j++)
            #pragma unroll
            for (int k = 0; k < 4; k++) acc[i][j][k] = 0.f;

    auto load_chunk = [&](int buf, int k0) {
        #pragma unroll
        for (int i = 0; i < 2; i++) {
            int idx = tid + i*256;
            int r = idx >> 2, kq = idx & 3;
            unsigned da = (unsigned)__cvta_generic_to_shared(&As[buf][r][kq*4]);
            const float* ga = Ag + (size_t)(row0 + r)*ND + k0 + kq*4;
            asm volatile("cp.async.ca.shared.global [%0], [%1], 16;\n" :: "r"(da), "l"(ga));
            unsigned db = (unsigned)__cvta_generic_to_shared(&Bs[buf][r][kq*4]);
            const float* gbp = Bg + (size_t)(col0 + r)*ND + k0 + kq*4;
            asm volatile("cp.async.ca.shared.global [%0], [%1], 16;\n" :: "r"(db), "l"(gbp));
        }
        asm volatile("cp.async.commit_group;\n");
    };

    load_chunk(0, 0);
    asm volatile("cp.async.wait_group 0;\n");
    __syncthreads();

    for (int c = 0; c < ND/KC; c++) {
        if (c < ND/KC - 1) load_chunk((c+1)&1, (c+1)*KC);
        int buf = c & 1;
        #pragma unroll
        for (int ks = 0; ks < 2; ks++) {
            int kb = ks*8;
            unsigned a[4][4], b[4][2];
            #pragma unroll
            for (int mf = 0; mf < 4; mf++) {
                int m = wm*64 + mf*16 + grp;
                a[mf][0] = __float_as_uint(As[buf][m    ][kb + t4]);
                a[mf][1] = __float_as_uint(As[buf][m + 8][kb + t4]);
                a[mf][2] = __float_as_uint(As[buf][m    ][kb + t4 + 4]);
                a[mf][3] = __float_as_uint(As[buf][m + 8][kb + t4 + 4]);
            }
            #pragma unroll
            for (int nf = 0; nf < 4; nf++) {
                int n = wn*32 + nf*8 + grp;
                b[nf][0] = __float_as_uint(Bs[buf][n][kb + t4]);
                b[nf][1] = __float_as_uint(Bs[buf][n][kb + t4 + 4]);
            }
            #pragma unroll
            for (int mf = 0; mf < 4; mf++)
                #pragma unroll
                for (int nf = 0; nf < 4; nf++)
                    MMA_TF32(acc[mf][nf], a[mf], b[nf]);
        }
        if (c < ND/KC - 1) {
            asm volatile("cp.async.wait_group 0;\n");
            __syncthreads();
        }
    }

    #pragma unroll
    for (int mf = 0; mf < 4; mf++) {
        int rlo = row0 + wm*64 + mf*16 + grp;
        int rhi = rlo + 8;
        float salo = sAg[rlo], sahi = sAg[rhi];
        #pragma unroll
        for (int nf = 0; nf < 4; nf++) {
            int col = col0 + wn*32 + nf*8 + t4*2;
            float2 sb2 = *(const float2*)&sBg[col];
            float2 olo = make_float2(salo + sb2.x - 2.0f*acc[mf][nf][0],
                                     salo + sb2.y - 2.0f*acc[mf][nf][1]);
            float2 ohi = make_float2(sahi + sb2.x - 2.0f*acc[mf][nf][2],
                                     sahi + sb2.y - 2.0f*acc[mf][nf][3]);
            *(float2*)&Dg[(size_t)rlo*NPER + col] = olo;
            *(float2*)&Dg[(size_t)rhi*NPER + col] = ohi;
        }
    }
}

// ---------------- 5) top-16: packed u64 keys + cached group minima ----------------
__global__ void __launch_bounds__(256) select_kernel(int mode) {
    const float* D      = mode ? g_DN    : g_DG;
    float*       rowsum = mode ? g_dnsum : g_dgsum;
    int*         idxout = mode ? (int*)0 : g_idx;

    int w = (blockIdx.x*blockDim.x + threadIdx.x) >> 5;
    int lane = threadIdx.x & 31;
    if (w >= NROWS) return;
    const float* dr = D + (size_t)w*NPER;

    unsigned long long key[32];
    #pragma unroll
    for (int t = 0; t < 8; t++) {
        float4 q = *(const float4*)(dr + t*128 + (lane<<2));
        int cb = t*128 + (lane<<2);
        key[t*4+0] = ((unsigned long long)__float_as_uint(fmaxf(q.x,1e-12f)) << 32) | (unsigned)(cb+0);
        key[t*4+1] = ((unsigned long long)__float_as_uint(fmaxf(q.y,1e-12f)) << 32) | (unsigned)(cb+1);
        key[t*4+2] = ((unsigned long long)__float_as_uint(fmaxf(q.z,1e-12f)) << 32) | (unsigned)(cb+2);
        key[t*4+3] = ((unsigned long long)__float_as_uint(fmaxf(q.w,1e-12f)) << 32) | (unsigned)(cb+3);
    }
    unsigned long long gm[4];
    #pragma unroll
    for (int g = 0; g < 4; g++) {
        unsigned long long m0 = u64min(key[g*8+0], key[g*8+1]);
        unsigned long long m1 = u64min(key[g*8+2], key[g*8+3]);
        unsigned long long m2 = u64min(key[g*8+4], key[g*8+5]);
        unsigned long long m3 = u64min(key[g*8+6], key[g*8+7]);
        gm[g] = u64min(u64min(m0,m1), u64min(m2,m3));
    }

    float sum = 0.f;
    for (int k = 0; k < KSEL; k++) {
        unsigned long long bm = u64min(u64min(gm[0],gm[1]), u64min(gm[2],gm[3]));
        #pragma unroll
        for (int o = 16; o; o >>= 1)
            bm = u64min(bm, __shfl_xor_sync(0xffffffffu, bm, o));
        float val = __uint_as_float((unsigned)(bm >> 32));
        int col = (int)(bm & 0x3ffu);
        sum += sqrtf(val);
        if (idxout && lane == 0) idxout[w*KSEL + k] = col;
        if (((col >> 2) & 31) == lane) {
            int i = ((col >> 7) << 2) | (col & 3);
            #pragma unroll
            for (int tt = 0; tt < 32; tt++) if (tt == i) key[tt] = ~0ULL;
            int g = i >> 3;
            #pragma unroll
            for (int gg = 0; gg < 4; gg++) if (gg == g) {
                unsigned long long m0 = u64min(key[gg*8+0], key[gg*8+1]);
                unsigned long long m1 = u64min(key[gg*8+2], key[gg*8+3]);
                unsigned long long m2 = u64min(key[gg*8+4], key[gg*8+5]);
                unsigned long long m3 = u64min(key[gg*8+6], key[gg*8+7]);
                gm[gg] = u64min(u64min(m0,m1), u64min(m2,m3));
            }
        }
    }
    if (!lane) rowsum[w] = sum;
}

// ---------------- 6) velocity distances at dg indices ----------------
__global__ void dv_kernel() {
    int w = (blockIdx.x*blockDim.x + threadIdx.x) >> 5;
    int lane = threadIdx.x & 31;
    if (w >= NROWS) return;
    int gb = w >> 10;
    const float* ve  = g_Ve + (size_t)w*ND;
    const float* vab = g_Va + ((size_t)gb << 10)*ND;
    float e[6];
    #pragma unroll
    for (int t = 0; t < 6; t++) e[t] = ve[t*32 + lane];
    float sum = 0.f;
    for (int k = 0; k < KSEL; k++) {
        int j = g_idx[w*KSEL + k];
        const float* va = vab + (size_t)j*ND;
        float s = 0.f;
        #pragma unroll
        for (int t = 0; t < 6; t++) { float d = e[t] - va[t*32 + lane]; s += d*d; }
        #pragma unroll
        for (int o = 16; o; o >>= 1) s += __shfl_xor_sync(0xffffffffu, s, o);
        sum += sqrtf(fmaxf(s, 1e-12f));
    }
    if (!lane) g_dvsum[w] = sum;
}

// ---------------- 7) final reduction ----------------
__global__ void reduce_kernel(float* __restrict__ out) {
    __shared__ float red[512];
    int a = blockIdx.x;
    int t = threadIdx.x;
    const float* X = (a==0) ? g_dgsum : (a==1) ? g_dnsum : g_dvsum;
    float s = 0.f;
    for (int i = t; i < NROWS; i += 512) s += X[i];
    red[t] = s;
    __syncthreads();
    for (int o = 256; o; o >>= 1) {
        if (t < o) red[t] += red[t+o];
        __syncthreads();
    }
    if (!t) out[a] = red[0] * (1.0f/(524288.0f*8.0f));
}

// ---------------- launch: interleaved dist/select for L2 reuse of D ----------------
extern "C" void kernel_launch(void* const* d_in, const int* in_sizes, int n_in,
                              void* d_out, int out_size) {
    const float* E = (const float*)d_in[0];
    const float* A = (const float*)d_in[1];
    float* out = (float*)d_out;

    rank_kernel<<<2, 256>>>(E, A);
    build_kernel<<<(2*NB*NF*NPTS)/256, 256>>>(E, A);
    stats_part<<<dim3(64,8), 768>>>();
    stats_final<<<64, 192>>>();
    apply_kernel<<<65536/8, 256>>>();
    dist_kernel<<<dim3(8,8,NGB), 256>>>(0);
    select_kernel<<<NROWS/8, 256>>>(0);     // consume DG while L2-resident
    dist_kernel<<<dim3(8,8,NGB), 256>>>(1);
    select_kernel<<<NROWS/8, 256>>>(1);     // consume DN while L2-resident
    dv_kernel<<<NROWS/8, 256>>>();
    reduce_kernel<<<3, 512>>>(out);
}

// round 17
// speedup vs baseline: 1.1538x; 1.1538x over previous
#include <cuda_runtime.h>
#include <cuda_fp16.h>
#include <math.h>
#include <float.h>

#define NB 4
#define NF 64
#define NPTS 8192
#define NC 11
#define NG 8
#define NPER 1024
#define ND 192            // NF*3
#define NGB 32            // NG*NB
#define KSEL 16
#define NROWS (NGB*NPER)  // 32768

// ---------------- static device scratch ----------------
__device__ __half g_Pe[NGB*NPER*ND];
__device__ __half g_Pa[NGB*NPER*ND];
__device__ __half g_NPe[NGB*NPER*ND];
__device__ __half g_NPa[NGB*NPER*ND];
__device__ float g_Ve[NGB*NPER*ND];
__device__ float g_Va[NGB*NPER*ND];
__device__ float g_sPe[NROWS], g_sPa[NROWS], g_sNPe[NROWS], g_sNPa[NROWS];
__device__ float g_DG[(size_t)NGB*NPER*NPER];
__device__ float g_DN[(size_t)NGB*NPER*NPER];
__device__ float g_dgsum[NROWS], g_dnsum[NROWS], g_dvsum[NROWS];
__device__ int   g_idx[NROWS*KSEL];
__device__ int   g_rank[2*NPTS];
__device__ float g_partS[64*8*ND];
__device__ float g_partQ[64*8*ND];
__device__ float g_mean[64*3];
__device__ float g_inv[64*NF];

__device__ __forceinline__ unsigned long long u64min(unsigned long long a, unsigned long long b) {
    return a < b ? a : b;
}

// ---------------- 1) fused group-id + stable counting sort -> rank ----------------
__global__ void rank_kernel(const float* __restrict__ E, const float* __restrict__ A) {
    __shared__ int sbg[NPTS];
    __shared__ int sh[NG][257];
    __shared__ int gbase[NG];
    int side = blockIdx.x;
    const float* X = side ? A : E;
    int t = threadIdx.x;
    int base = t*32;
    int cnt[NG];
    #pragma unroll
    for (int g = 0; g < NG; g++) cnt[g] = 0;
    for (int i = 0; i < 32; i++) {
        int p = base + i;
        float best = -FLT_MAX; int bi = 0;
        #pragma unroll
        for (int c = 0; c < NG; c++) {
            float v = X[(size_t)p*NC + 3 + c];
            if (v > best) { best = v; bi = c; }
        }
        sbg[p] = bi;
        cnt[bi]++;
    }
    #pragma unroll
    for (int g = 0; g < NG; g++) sh[g][t] = cnt[g];
    __syncthreads();
    if (t < NG) {
        int acc = 0;
        for (int i = 0; i < 256; i++) { int c = sh[t][i]; sh[t][i] = acc; acc += c; }
        sh[t][256] = acc;
    }
    __syncthreads();
    if (t == 0) {
        int acc = 0;
        for (int g = 0; g < NG; g++) { gbase[g] = acc; acc += sh[g][256]; }
    }
    __syncthreads();
    int run[NG];
    #pragma unroll
    for (int g = 0; g < NG; g++) run[g] = gbase[g] + sh[g][t];
    int* rk = g_rank + side*NPTS;
    for (int i = 0; i < 32; i++) { int g = sbg[base+i]; rk[base+i] = run[g]++; }
}

// ---------------- 2) build packed positions (fp16) ----------------
__global__ void build_kernel(const float* __restrict__ E, const float* __restrict__ A) {
    int tid = blockIdx.x*blockDim.x + threadIdx.x;
    int side = tid >> 21;
    int lin  = tid & ((1<<21)-1);
    int p = lin & (NPTS-1);
    int f = (lin >> 13) & (NF-1);
    int b = lin >> 19;
    const float* X = side ? A : E;
    size_t base = ((size_t)(b*NF + f)*NPTS + p)*NC;
    float x = X[base], y = X[base+1], z = X[base+2];
    int rk = g_rank[side*NPTS + p];
    int g = rk >> 10, j = rk & (NPER-1);
    int gb = g*NB + b;
    size_t o = ((size_t)(gb*NPER + j))*ND + f*3;
    __half* P = side ? g_Pa : g_Pe;
    P[o] = __float2half_rn(x); P[o+1] = __float2half_rn(y); P[o+2] = __float2half_rn(z);
}

// ---------------- 3a) partial column sums (reads fp16) ----------------
__global__ void __launch_bounds__(768) stats_part() {
    int sgb = blockIdx.x;
    int slice = blockIdx.y;
    int side = sgb >> 5, gb = sgb & 31;
    const __half* P = (side ? g_Pa : g_Pe) + (size_t)gb*NPER*ND;
    int t = threadIdx.x % ND;
    int r = threadIdx.x / ND;
    __shared__ float Ss[4][ND];
    __shared__ float Qs[4][ND];
    float s = 0.f, q = 0.f;
    int j0 = slice*128;
    #pragma unroll 4
    for (int j = j0 + r; j < j0 + 128; j += 4) {
        float x = __half2float(P[(size_t)j*ND + t]);
        s += x; q += x*x;
    }
    Ss[r][t] = s; Qs[r][t] = q;
    __syncthreads();
    if (r == 0) {
        g_partS[(sgb*8 + slice)*ND + t] = Ss[0][t]+Ss[1][t]+Ss[2][t]+Ss[3][t];
        g_partQ[(sgb*8 + slice)*ND + t] = Qs[0][t]+Qs[1][t]+Qs[2][t]+Qs[3][t];
    }
}

// ---------------- 3b) finalize mean / invstd ----------------
__global__ void stats_final() {
    int sgb = blockIdx.x;
    int t = threadIdx.x;
    __shared__ float Ss[ND];
    __shared__ float Qs[ND];
    __shared__ float mean[3];
    float S = 0.f, Q = 0.f;
    #pragma unroll
    for (int sl = 0; sl < 8; sl++) {
        S += g_partS[(sgb*8 + sl)*ND + t];
        Q += g_partQ[(sgb*8 + sl)*ND + t];
    }
    Ss[t] = S; Qs[t] = Q;
    __syncthreads();
    if (t < 3) {
        float m = 0.f;
        for (int ff = 0; ff < NF; ff++) m += Ss[ff*3 + t];
        mean[t] = m / 65536.0f;
        g_mean[sgb*3 + t] = mean[t];
    }
    __syncthreads();
    if (t < NF) {
        float Sc = 0.f, Qc = 0.f;
        #pragma unroll
        for (int dd = 0; dd < 3; dd++) {
            float mu = mean[dd];
            float Sx = Ss[t*3+dd], Qx = Qs[t*3+dd];
            Sc += Sx - 1024.0f*mu;
            Qc += Qx - 2.0f*mu*Sx + 1024.0f*mu*mu;
        }
        float var = (Qc - Sc*Sc/3072.0f) / 3071.0f;   // ddof=1
        g_inv[sgb*NF + t] = 1.0f / sqrtf(fmaxf(var, 1e-30f));
    }
}

// ---------------- 3c) apply: normalize (fp16) + velocity (fp32) + row sqnorms ----------------
__global__ void __launch_bounds__(256) apply_kernel() {
    int w = blockIdx.x*8 + (threadIdx.x >> 5);
    int lane = threadIdx.x & 31;
    int side = w >> 15;
    int gb = (w >> 10) & 31;
    int j = w & (NPER-1);

    __shared__ float mu[3];
    __shared__ float inv[NF];
    int sgb0 = (blockIdx.x*8) >> 10;
    if (threadIdx.x < 3)  mu[threadIdx.x]  = g_mean[sgb0*3 + threadIdx.x];
    if (threadIdx.x < NF) inv[threadIdx.x] = g_inv[sgb0*NF + threadIdx.x];
    __syncthreads();

    size_t off = ((size_t)(gb*NPER + j))*ND;
    const __half* P = (side ? g_Pa : g_Pe) + off;
    __half* NP = (side ? g_NPa : g_NPe) + off;
    float*  V  = (side ? g_Va  : g_Ve ) + off;

    float sP = 0.f, sNP = 0.f, prev = 0.f;
    #pragma unroll
    for (int i = 0; i < 6; i++) {
        int c = i*32 + lane;
        float x = __half2float(P[c]);
        float xm3a = __shfl_up_sync(0xffffffffu, x, 3);
        float xm3b = __shfl_sync(0xffffffffu, prev, (lane + 29) & 31);
        float xm3 = (lane >= 3) ? xm3a : xm3b;
        float v = (i == 0 && lane < 3) ? 0.f : (x - xm3);
        int d = c % 3, f = c / 3;
        __half nh = __float2half_rn((x - mu[d]) * inv[f]);
        float nq = __half2float(nh);
        NP[c] = nh;
        V[c] = v;
        sP += x*x; sNP += nq*nq;
        prev = x;
    }
    #pragma unroll
    for (int o = 16; o; o >>= 1) {
        sP  += __shfl_down_sync(0xffffffffu, sP,  o);
        sNP += __shfl_down_sync(0xffffffffu, sNP, o);
    }
    if (!lane) {
        int row = w & (NROWS-1);
        (side ? g_sPa  : g_sPe )[row] = sP;
        (side ? g_sNPa : g_sNPe)[row] = sNP;
    }
}

// ---------------- 4) distance^2 via fp16 m16n8k16 mma.sync (merged modes) ----------------
#define MMA_F16(d, a, b) \
    asm volatile("mma.sync.aligned.m16n8k16.row.col.f32.f16.f16.f32 " \
        "{%0,%1,%2,%3}, {%4,%5,%6,%7}, {%8,%9}, {%0,%1,%2,%3};\n" \
        : "+f"(d[0]), "+f"(d[1]), "+f"(d[2]), "+f"(d[3]) \
        : "r"(a[0]), "r"(a[1]), "r"(a[2]), "r"(a[3]), "r"(b[0]), "r"(b[1]))

#define KCH 32          // k-halves per chunk
#define RSH 40          // row stride in halves (32 + 8 pad -> 20 words, conflict-free)

__global__ void __launch_bounds__(256) dist_kernel() {
    int z = blockIdx.z;
    int mode = z >> 5, gb = z & 31;
    const __half* A   = mode ? g_NPe  : g_Pe;
    const __half* Bm  = mode ? g_NPa  : g_Pa;
    const float*  sA  = mode ? g_sNPe : g_sPe;
    const float*  sB  = mode ? g_sNPa : g_sPa;
    float*        D   = mode ? g_DN   : g_DG;

    const __half* Ag = A  + (size_t)gb*NPER*ND;
    const __half* Bg = Bm + (size_t)gb*NPER*ND;
    float*        Dg = D  + (size_t)gb*NPER*NPER;
    const float* sAg = sA + gb*NPER;
    const float* sBg = sB + gb*NPER;
    int row0 = blockIdx.y*128, col0 = blockIdx.x*128;

    __shared__ __half As[2][128][RSH];
    __shared__ __half Bs[2][128][RSH];

    int tid = threadIdx.x;
    int lane = tid & 31, wid = tid >> 5;
    int wm = wid >> 2, wn = wid & 3;
    int grp = lane >> 2, t4 = lane & 3;

    float acc[4][4][4];
    #pragma unroll
    for (int i = 0; i < 4; i++)
        #pragma unroll
        for (int j = 0; j < 4; j++)
            #pragma unroll
            for (int k = 0; k < 4; k++) acc[i][j][k] = 0.f;

    // chunk = 128 rows x 32 halves (64B/row = 4 x 16B)
    auto load_chunk = [&](int buf, int k0) {
        #pragma unroll
        for (int i = 0; i < 2; i++) {
            int idx = tid + i*256;
            int r = idx >> 2, kq = idx & 3;
            unsigned da = (unsigned)__cvta_generic_to_shared(&As[buf][r][kq*8]);
            const __half* ga = Ag + (size_t)(row0 + r)*ND + k0 + kq*8;
            asm volatile("cp.async.ca.shared.global [%0], [%1], 16;\n" :: "r"(da), "l"(ga));
            unsigned db = (unsigned)__cvta_generic_to_shared(&Bs[buf][r][kq*8]);
            const __half* gbp = Bg + (size_t)(col0 + r)*ND + k0 + kq*8;
            asm volatile("cp.async.ca.shared.global [%0], [%1], 16;\n" :: "r"(db), "l"(gbp));
        }
        asm volatile("cp.async.commit_group;\n");
    };

    load_chunk(0, 0);
    asm volatile("cp.async.wait_group 0;\n");
    __syncthreads();

    for (int c = 0; c < ND/KCH; c++) {        // 6 chunks
        if (c < ND/KCH - 1) load_chunk((c+1)&1, (c+1)*KCH);
        int buf = c & 1;
        #pragma unroll
        for (int ks = 0; ks < 2; ks++) {      // two k16 steps per chunk
            int kb = ks*16;
            unsigned a[4][4], b[4][2];
            #pragma unroll
            for (int mf = 0; mf < 4; mf++) {
                int m = wm*64 + mf*16 + grp;
                a[mf][0] = *(const unsigned*)&As[buf][m    ][kb + 2*t4];
                a[mf][1] = *(const unsigned*)&As[buf][m + 8][kb + 2*t4];
                a[mf][2] = *(const unsigned*)&As[buf][m    ][kb + 2*t4 + 8];
                a[mf][3] = *(const unsigned*)&As[buf][m + 8][kb + 2*t4 + 8];
            }
            #pragma unroll
            for (int nf = 0; nf < 4; nf++) {
                int n = wn*32 + nf*8 + grp;
                b[nf][0] = *(const unsigned*)&Bs[buf][n][kb + 2*t4];
                b[nf][1] = *(const unsigned*)&Bs[buf][n][kb + 2*t4 + 8];
            }
            #pragma unroll
            for (int mf = 0; mf < 4; mf++)
                #pragma unroll
                for (int nf = 0; nf < 4; nf++)
                    MMA_F16(acc[mf][nf], a[mf], b[nf]);
        }
        if (c < ND/KCH - 1) {
            asm volatile("cp.async.wait_group 0;\n");
            __syncthreads();
        }
    }

    #pragma unroll
    for (int mf = 0; mf < 4; mf++) {
        int rlo = row0 + wm*64 + mf*16 + grp;
        int rhi = rlo + 8;
        float salo = sAg[rlo], sahi = sAg[rhi];
        #pragma unroll
        for (int nf = 0; nf < 4; nf++) {
            int col = col0 + wn*32 + nf*8 + t4*2;
            float2 sb2 = *(const float2*)&sBg[col];
            float2 olo = make_float2(salo + sb2.x - 2.0f*acc[mf][nf][0],
                                     salo + sb2.y - 2.0f*acc[mf][nf][1]);
            float2 ohi = make_float2(sahi + sb2.x - 2.0f*acc[mf][nf][2],
                                     sahi + sb2.y - 2.0f*acc[mf][nf][3]);
            *(float2*)&Dg[(size_t)rlo*NPER + col] = olo;
            *(float2*)&Dg[(size_t)rhi*NPER + col] = ohi;
        }
    }
}

// ---------------- 5) top-16 (merged modes): packed u64 keys ----------------
__global__ void __launch_bounds__(256) select_kernel() {
    int w = (blockIdx.x*blockDim.x + threadIdx.x) >> 5;   // 0 .. 2*NROWS-1
    int lane = threadIdx.x & 31;
    if (w >= 2*NROWS) return;
    int mode = w >> 15;
    int row = w & (NROWS-1);
    const float* D      = mode ? g_DN    : g_DG;
    float*       rowsum = mode ? g_dnsum : g_dgsum;
    int*         idxout = mode ? (int*)0 : g_idx;
    const float* dr = D + (size_t)row*NPER;

    unsigned long long key[32];
    #pragma unroll
    for (int t = 0; t < 8; t++) {
        float4 q = *(const float4*)(dr + t*128 + (lane<<2));
        int cb = t*128 + (lane<<2);
        key[t*4+0] = ((unsigned long long)__float_as_uint(fmaxf(q.x,1e-12f)) << 32) | (unsigned)(cb+0);
        key[t*4+1] = ((unsigned long long)__float_as_uint(fmaxf(q.y,1e-12f)) << 32) | (unsigned)(cb+1);
        key[t*4+2] = ((unsigned long long)__float_as_uint(fmaxf(q.z,1e-12f)) << 32) | (unsigned)(cb+2);
        key[t*4+3] = ((unsigned long long)__float_as_uint(fmaxf(q.w,1e-12f)) << 32) | (unsigned)(cb+3);
    }
    unsigned long long gm[4];
    #pragma unroll
    for (int g = 0; g < 4; g++) {
        unsigned long long m0 = u64min(key[g*8+0], key[g*8+1]);
        unsigned long long m1 = u64min(key[g*8+2], key[g*8+3]);
        unsigned long long m2 = u64min(key[g*8+4], key[g*8+5]);
        unsigned long long m3 = u64min(key[g*8+6], key[g*8+7]);
        gm[g] = u64min(u64min(m0,m1), u64min(m2,m3));
    }

    float sum = 0.f;
    for (int k = 0; k < KSEL; k++) {
        unsigned long long bm = u64min(u64min(gm[0],gm[1]), u64min(gm[2],gm[3]));
        #pragma unroll
        for (int o = 16; o; o >>= 1)
            bm = u64min(bm, __shfl_xor_sync(0xffffffffu, bm, o));
        float val = __uint_as_float((unsigned)(bm >> 32));
        int col = (int)(bm & 0x3ffu);
        sum += sqrtf(val);
        if (idxout && lane == 0) idxout[row*KSEL + k] = col;
        if (((col >> 2) & 31) == lane) {
            int i = ((col >> 7) << 2) | (col & 3);
            #pragma unroll
            for (int tt = 0; tt < 32; tt++) if (tt == i) key[tt] = ~0ULL;
            int g = i >> 3;
            #pragma unroll
            for (int gg = 0; gg < 4; gg++) if (gg == g) {
                unsigned long long m0 = u64min(key[gg*8+0], key[gg*8+1]);
                unsigned long long m1 = u64min(key[gg*8+2], key[gg*8+3]);
                unsigned long long m2 = u64min(key[gg*8+4], key[gg*8+5]);
                unsigned long long m3 = u64min(key[gg*8+6], key[gg*8+7]);
                gm[gg] = u64min(u64min(m0,m1), u64min(m2,m3));
            }
        }
    }
    if (!lane) rowsum[row] = sum;
}

// ---------------- 6) velocity distances at dg indices ----------------
__global__ void dv_kernel() {
    int w = (blockIdx.x*blockDim.x + threadIdx.x) >> 5;
    int lane = threadIdx.x & 31;
    if (w >= NROWS) return;
    int gb = w >> 10;
    const float* ve  = g_Ve + (size_t)w*ND;
    const float* vab = g_Va + ((size_t)gb << 10)*ND;
    float e[6];
    #pragma unroll
    for (int t = 0; t < 6; t++) e[t] = ve[t*32 + lane];
    float sum = 0.f;
    for (int k = 0; k < KSEL; k++) {
        int j = g_idx[w*KSEL + k];
        const float* va = vab + (size_t)j*ND;
        float s = 0.f;
        #pragma unroll
        for (int t = 0; t < 6; t++) { float d = e[t] - va[t*32 + lane]; s += d*d; }
        #pragma unroll
        for (int o = 16; o; o >>= 1) s += __shfl_xor_sync(0xffffffffu, s, o);
        sum += sqrtf(fmaxf(s, 1e-12f));
    }
    if (!lane) g_dvsum[w] = sum;
}

// ---------------- 7) final reduction ----------------
__global__ void reduce_kernel(float* __restrict__ out) {
    __shared__ float red[512];
    int a = blockIdx.x;
    int t = threadIdx.x;
    const float* X = (a==0) ? g_dgsum : (a==1) ? g_dnsum : g_dvsum;
    float s = 0.f;
    for (int i = t; i < NROWS; i += 512) s += X[i];
    red[t] = s;
    __syncthreads();
    for (int o = 256; o; o >>= 1) {
        if (t < o) red[t] += red[t+o];
        __syncthreads();
    }
    if (!t) out[a] = red[0] * (1.0f/(524288.0f*8.0f));
}

// ---------------- launch ----------------
extern "C" void kernel_launch(void* const* d_in, const int* in_sizes, int n_in,
                              void* d_out, int out_size) {
    const float* E = (const float*)d_in[0];
    const float* A = (const float*)d_in[1];
    float* out = (float*)d_out;

    rank_kernel<<<2, 256>>>(E, A);
    build_kernel<<<(2*NB*NF*NPTS)/256, 256>>>(E, A);
    stats_part<<<dim3(64,8), 768>>>();
    stats_final<<<64, 192>>>();
    apply_kernel<<<65536/8, 256>>>();
    dist_kernel<<<dim3(8,8,64), 256>>>();        // both modes, grid.z = 2*NGB
    select_kernel<<<(2*NROWS)/8, 256>>>();       // both modes
    dv_kernel<<<NROWS/8, 256>>>();
    reduce_kernel<<<3, 512>>>(out);
}